// round 3
// baseline (speedup 1.0000x reference)
#include <cuda_runtime.h>
#include <math_constants.h>

#define HH   16
#define LL   8192
#define DD   64
#define MB   128
#define NBLK 128
#define TSEL 16

// scratch (no allocation allowed -> device globals)
__device__ float g_kmean[HH * DD];
__device__ float g_qpool[HH * MB * DD];
__device__ float g_kpool[HH * NBLK * DD];
__device__ int   g_lut[HH * MB * TSEL];

// ---------- f32x2 helpers (Blackwell packed fp32) ----------
static __device__ __forceinline__ unsigned long long pk2(float x, float y) {
    unsigned long long r;
    asm("mov.b64 %0, {%1, %2};" : "=l"(r) : "f"(x), "f"(y));
    return r;
}
static __device__ __forceinline__ void upk2(unsigned long long v, float& x, float& y) {
    asm("mov.b64 {%0, %1}, %2;" : "=f"(x), "=f"(y) : "l"(v));
}
static __device__ __forceinline__ void fma2(unsigned long long& d,
                                            unsigned long long a,
                                            unsigned long long b) {
    asm("fma.rn.f32x2 %0, %1, %2, %0;" : "+l"(d) : "l"(a), "l"(b));
}
static __device__ __forceinline__ unsigned long long mul2(unsigned long long a,
                                                          unsigned long long b) {
    unsigned long long r;
    asm("mul.rn.f32x2 %0, %1, %2;" : "=l"(r) : "l"(a), "l"(b));
    return r;
}

// ---------- Kernel A: k mean over L per (h, d) ----------
__global__ void kmean_kernel(const float* __restrict__ k) {
    __shared__ float red[512];
    const int h = blockIdx.x;
    const int t = threadIdx.x;
    const int d = t & 63;
    const int g = t >> 6;  // 0..7, each covers 1024 rows
    const float* src = k + ((size_t)h * LL + (size_t)g * 1024) * DD + d;
    float s = 0.f;
#pragma unroll 8
    for (int r = 0; r < 1024; ++r) s += src[(size_t)r * DD];
    red[t] = s;
    __syncthreads();
    if (t < 64) {
        float tot = 0.f;
#pragma unroll
        for (int gg = 0; gg < 8; ++gg) tot += red[t + 64 * gg];
        g_kmean[h * DD + t] = tot * (1.f / 8192.f);
    }
}

// ---------- Kernel B: block pools. z=0 -> q_pool, z=1 -> k_pool (mean-centered) ----------
__global__ void pool_kernel(const float* __restrict__ q, const float* __restrict__ k) {
    const int m = blockIdx.x;
    const int h = blockIdx.y;
    const int d = threadIdx.x;
    const float* base = (blockIdx.z == 0 ? q : k);
    const float* src = base + ((size_t)h * LL + (size_t)m * 64) * DD + d;
    float s = 0.f;
#pragma unroll 8
    for (int r = 0; r < 64; ++r) s += src[r * DD];
    s *= (1.f / 64.f);
    if (blockIdx.z == 0)
        g_qpool[(h * MB + m) * DD + d] = s;
    else
        g_kpool[(h * NBLK + m) * DD + d] = s - g_kmean[h * DD + d];
}

// ---------- Kernel C: block scores + top-16 LUT per (h, m) ----------
__global__ void lut_kernel() {
    __shared__ float qrow[64];
    __shared__ float kp[128 * 65];  // padded stride 65 -> conflict-free row reads
    __shared__ float sc[128];
    const int m = blockIdx.x;
    const int h = blockIdx.y;
    const int t = threadIdx.x;

    if (t < 64) qrow[t] = g_qpool[(h * MB + m) * DD + t];
    for (int i = t; i < 128 * 64; i += 128) {
        int n = i >> 6, d = i & 63;
        kp[n * 65 + d] = g_kpool[(h * NBLK + n) * DD + d];
    }
    __syncthreads();

    float acc = 0.f;
#pragma unroll 8
    for (int d = 0; d < 64; ++d) acc += qrow[d] * kp[t * 65 + d];
    sc[t] = acc;
    __syncthreads();

    if (t < 32) {
        for (int r = 0; r < TSEL; ++r) {
            float bv = -CUDART_INF_F;
            int bi = 0;
#pragma unroll
            for (int kk = 0; kk < 4; ++kk) {
                int n = t + 32 * kk;
                float v = sc[n];
                if (v > bv || (v == bv && n < bi)) { bv = v; bi = n; }
            }
#pragma unroll
            for (int s = 16; s > 0; s >>= 1) {
                float ov = __shfl_xor_sync(0xffffffffu, bv, s);
                int   oi = __shfl_xor_sync(0xffffffffu, bi, s);
                if (ov > bv || (ov == bv && oi < bi)) { bv = ov; bi = oi; }
            }
            if (t == 0) {
                g_lut[(h * MB + m) * TSEL + r] = bi;
                sc[bi] = -CUDART_INF_F;
            }
            __syncwarp();
        }
    }
}

// ---------- Kernel D: sparse attention main kernel ----------
// smem layout (floats): Q2[64][128] dup'd+scaled | KT[64][64] | V[64][64] | P2[64][128] dup'd | lut[16]
#define SM_Q2 0
#define SM_KT 8192
#define SM_V  12288
#define SM_P2 16384
#define SM_LUT_BYTES (24576 * 4)
#define SMEM_BYTES (SM_LUT_BYTES + 64)

__global__ __launch_bounds__(256) void attn_kernel(const float* __restrict__ q,
                                                   const float* __restrict__ k,
                                                   const float* __restrict__ v,
                                                   float* __restrict__ out) {
    extern __shared__ float sm[];
    float* Q2 = sm + SM_Q2;
    float* KT = sm + SM_KT;
    float* Vs = sm + SM_V;
    float* P2 = sm + SM_P2;
    int* lut = (int*)(sm + 24576);

    const int m = blockIdx.x;
    const int h = blockIdx.y;
    const int t = threadIdx.x;
    const int tx = t & 15;   // 16 column groups (4 cols each)
    const int ty = t >> 4;   // 16 row groups (4 rows each)
    const int c = t & 63;    // copy-lane: row within block
    const int dg0 = t >> 6;  // copy-lane: chunk group

    // ---- build duplicated, pre-scaled Q2[d][2q] = Q[q][d] * 0.125 ----
    {
        const float* qg = q + ((size_t)h * LL + (size_t)m * 64) * DD;
#pragma unroll
        for (int it = 0; it < 4; ++it) {
            int dc = dg0 + 4 * it;  // 0..15
            float4 qq = *(const float4*)(qg + c * DD + dc * 4);
            qq.x *= 0.125f; qq.y *= 0.125f; qq.z *= 0.125f; qq.w *= 0.125f;
            *(unsigned long long*)(Q2 + (dc * 4 + 0) * 128 + 2 * c) = pk2(qq.x, qq.x);
            *(unsigned long long*)(Q2 + (dc * 4 + 1) * 128 + 2 * c) = pk2(qq.y, qq.y);
            *(unsigned long long*)(Q2 + (dc * 4 + 2) * 128 + 2 * c) = pk2(qq.z, qq.z);
            *(unsigned long long*)(Q2 + (dc * 4 + 3) * 128 + 2 * c) = pk2(qq.w, qq.w);
        }
    }
    if (t < TSEL) lut[t] = g_lut[(h * MB + m) * TSEL + t];

    unsigned long long o2[4][2];
    float mrow[4], lrow[4];
#pragma unroll
    for (int i = 0; i < 4; ++i) {
        mrow[i] = -CUDART_INF_F;
        lrow[i] = 0.f;
        o2[i][0] = 0ull; o2[i][1] = 0ull;
    }

    const float* kg = k + (size_t)h * LL * DD;
    const float* vg = v + (size_t)h * LL * DD;

    for (int bt = 0; bt < TSEL; ++bt) {
        __syncthreads();  // previous O-GEMM done with V/P2; Q2 build done (iter 0)
        const int nb = lut[bt];
        const float* kb = kg + (size_t)nb * 64 * DD;
        const float* vb = vg + (size_t)nb * 64 * DD;

        // ---- load K transposed: KT[d][c] = K[c][d]; stores hit distinct banks (c%32) ----
#pragma unroll
        for (int it = 0; it < 4; ++it) {
            int dc = dg0 + 4 * it;
            float4 kk = *(const float4*)(kb + c * DD + dc * 4);
            KT[(dc * 4 + 0) * 64 + c] = kk.x;
            KT[(dc * 4 + 1) * 64 + c] = kk.y;
            KT[(dc * 4 + 2) * 64 + c] = kk.z;
            KT[(dc * 4 + 3) * 64 + c] = kk.w;
        }
        // ---- load V natural (coalesced) ----
#pragma unroll
        for (int r = 0; r < 4; ++r) {
            int i4 = t + 256 * r;
            *(float4*)(Vs + i4 * 4) = *(const float4*)(vb + i4 * 4);
        }
        __syncthreads();

        // ---- S = (Q*scale) @ K^T, f32x2: lanes = column pairs ----
        unsigned long long s2[4][2];
#pragma unroll
        for (int i = 0; i < 4; ++i) { s2[i][0] = 0ull; s2[i][1] = 0ull; }
#pragma unroll 4
        for (int d = 0; d < 64; ++d) {
            const ulonglong2 kbp = *(const ulonglong2*)(KT + d * 64 + 4 * tx);
            const ulonglong2 qa = *(const ulonglong2*)(Q2 + d * 128 + 8 * ty);      // rows 4ty, 4ty+1 (dup'd)
            const ulonglong2 qb = *(const ulonglong2*)(Q2 + d * 128 + 8 * ty + 4);  // rows 4ty+2, 4ty+3
            fma2(s2[0][0], qa.x, kbp.x); fma2(s2[0][1], qa.x, kbp.y);
            fma2(s2[1][0], qa.y, kbp.x); fma2(s2[1][1], qa.y, kbp.y);
            fma2(s2[2][0], qb.x, kbp.x); fma2(s2[2][1], qb.x, kbp.y);
            fma2(s2[3][0], qb.y, kbp.x); fma2(s2[3][1], qb.y, kbp.y);
        }

        // ---- online softmax (row stats replicated across the 16-lane tx group) ----
        float p[4][4];
#pragma unroll
        for (int i = 0; i < 4; ++i) {
            float a, b, cc, dd2;
            upk2(s2[i][0], a, b);
            upk2(s2[i][1], cc, dd2);
            float mx = fmaxf(fmaxf(a, b), fmaxf(cc, dd2));
#pragma unroll
            for (int s = 8; s > 0; s >>= 1)
                mx = fmaxf(mx, __shfl_xor_sync(0xffffffffu, mx, s));
            float mnew = fmaxf(mrow[i], mx);
            float alpha = __expf(mrow[i] - mnew);
            mrow[i] = mnew;
            float p0 = __expf(a - mnew), p1 = __expf(b - mnew);
            float p2v = __expf(cc - mnew), p3 = __expf(dd2 - mnew);
            float rs = (p0 + p1) + (p2v + p3);
#pragma unroll
            for (int s = 8; s > 0; s >>= 1)
                rs += __shfl_xor_sync(0xffffffffu, rs, s);
            lrow[i] = lrow[i] * alpha + rs;
            unsigned long long al2 = pk2(alpha, alpha);
            o2[i][0] = mul2(o2[i][0], al2);
            o2[i][1] = mul2(o2[i][1], al2);
            p[i][0] = p0; p[i][1] = p1; p[i][2] = p2v; p[i][3] = p3;
        }

        // ---- store P duplicated: P2[r][2c] = P2[r][2c+1] = P[r][c] ----
#pragma unroll
        for (int i = 0; i < 4; ++i) {
            float* pr = P2 + (4 * ty + i) * 128 + 8 * tx;
            *(unsigned long long*)(pr + 0) = pk2(p[i][0], p[i][0]);
            *(unsigned long long*)(pr + 2) = pk2(p[i][1], p[i][1]);
            *(unsigned long long*)(pr + 4) = pk2(p[i][2], p[i][2]);
            *(unsigned long long*)(pr + 6) = pk2(p[i][3], p[i][3]);
        }
        __syncthreads();

        // ---- O += P @ V, f32x2: lanes = dim pairs ----
#pragma unroll 2
        for (int c0 = 0; c0 < 64; c0 += 2) {
            const ulonglong2 v0 = *(const ulonglong2*)(Vs + c0 * 64 + 4 * tx);
            const ulonglong2 v1 = *(const ulonglong2*)(Vs + (c0 + 1) * 64 + 4 * tx);
#pragma unroll
            for (int i = 0; i < 4; ++i) {
                const ulonglong2 pa = *(const ulonglong2*)(P2 + (4 * ty + i) * 128 + 2 * c0);
                fma2(o2[i][0], pa.x, v0.x); fma2(o2[i][1], pa.x, v0.y);
                fma2(o2[i][0], pa.y, v1.x); fma2(o2[i][1], pa.y, v1.y);
            }
        }
    }

    // ---- normalize and write out ----
    float* og = out + ((size_t)h * LL + (size_t)m * 64) * DD;
#pragma unroll
    for (int i = 0; i < 4; ++i) {
        float inv = 1.0f / lrow[i];
        float a, b, cc, dd2;
        upk2(o2[i][0], a, b);
        upk2(o2[i][1], cc, dd2);
        float4 r4 = make_float4(a * inv, b * inv, cc * inv, dd2 * inv);
        *(float4*)(og + (4 * ty + i) * DD + 4 * tx) = r4;
    }
}

extern "C" void kernel_launch(void* const* d_in, const int* in_sizes, int n_in,
                              void* d_out, int out_size) {
    const float* q = (const float*)d_in[0];
    const float* k = (const float*)d_in[1];
    const float* v = (const float*)d_in[2];
    float* out = (float*)d_out;

    cudaFuncSetAttribute(attn_kernel, cudaFuncAttributeMaxDynamicSharedMemorySize, SMEM_BYTES);

    kmean_kernel<<<HH, 512>>>(k);
    pool_kernel<<<dim3(MB, HH, 2), 64>>>(q, k);
    lut_kernel<<<dim3(MB, HH), 128>>>();
    attn_kernel<<<dim3(MB, HH), 256, SMEM_BYTES>>>(q, k, v, out);
}